// round 4
// baseline (speedup 1.0000x reference)
#include <cuda_runtime.h>
#include <cstdint>

#define NNODES 50000
#define MAXEDGES 800000
#define HID 128
#define EMB 64
#define KCLUS 10

// ---------------- scratch (device globals; no allocation allowed) ----------------
__device__ float g_xw  [NNODES * HID];        // x @ w1
__device__ float g_h   [NNODES * HID];        // relu(spmm + b1)
__device__ float g_hw  [NNODES * EMB];        // h @ w2
__device__ float g_zcat[NNODES * 3 * EMB];    // concat(z0,z1,z2)
__device__ int   g_cnt [NNODES];
__device__ int   g_off [NNODES + 1];
__device__ int   g_cur [NNODES];
__device__ int   g_scols[MAXEDGES];
__device__ float g_svals[MAXEDGES];
__device__ int   g_bsum[64];                  // block sums for hierarchical scan

// =================================================================================
// Tiled fp32 SGEMM v2: C[M,nc] = A[M,K] @ B[K,nc] (+bias,relu)
// 8x8 microtile split 4+4 (conflict-free smem reads), double-buffered smem,
// register prefetch, one __syncthreads per k-tile.
// =================================================================================
template<int BMv, int BNv, int BKv, int NT, bool BIAS_RELU>
__global__ void __launch_bounds__(NT)
sgemm_tile(const float* __restrict__ A, const float* __restrict__ B,
           const float* __restrict__ bias, float* __restrict__ C,
           int M, int K, int nc)
{
    constexpr int TX = BNv / 8;                 // threads along n
    constexpr int TY = BMv / 8;                 // threads along m
    static_assert(TX * TY == NT, "thread grid");
    constexpr int NA = (BMv * BKv) / (4 * NT);  // float4 A loads per thread
    constexpr int NB = (BKv * BNv) / (4 * NT);  // float4 B loads per thread
    constexpr int MH = BMv / 2;
    constexpr int NH = BNv / 2;

    __shared__ float As[2][BKv][BMv + 4];
    __shared__ float Bs[2][BKv][BNv];

    const int tid = threadIdx.x;
    const int ty  = tid / TX;
    const int tx  = tid % TX;
    const int bm  = blockIdx.x * BMv;
    const int bn  = blockIdx.y * BNv;

    float acc[8][8];
    #pragma unroll
    for (int i = 0; i < 8; i++)
        #pragma unroll
        for (int j = 0; j < 8; j++) acc[i][j] = 0.f;

    float4 pa[NA], pb[NB];

    // ---- global load helpers (predicated, zero-fill) ----
    auto loadG = [&](int k0) {
        #pragma unroll
        for (int i = 0; i < NA; i++) {
            int idx = tid + i * NT;
            int r   = idx / (BKv / 4);
            int c4  = idx % (BKv / 4);
            float4 v = make_float4(0.f, 0.f, 0.f, 0.f);
            int kk = k0 + c4 * 4;
            if ((bm + r) < M && kk < K)
                v = *(const float4*)(A + (size_t)(bm + r) * K + kk);
            pa[i] = v;
        }
        #pragma unroll
        for (int i = 0; i < NB; i++) {
            int idx = tid + i * NT;
            int r   = idx / (BNv / 4);
            int c4  = idx % (BNv / 4);
            float4 v = make_float4(0.f, 0.f, 0.f, 0.f);
            if ((k0 + r) < K)
                v = *(const float4*)(B + (size_t)(k0 + r) * nc + bn + c4 * 4);
            pb[i] = v;
        }
    };
    auto storeS = [&](int buf) {
        #pragma unroll
        for (int i = 0; i < NA; i++) {
            int idx = tid + i * NT;
            int r   = idx / (BKv / 4);
            int c4  = idx % (BKv / 4);
            As[buf][c4 * 4 + 0][r] = pa[i].x;
            As[buf][c4 * 4 + 1][r] = pa[i].y;
            As[buf][c4 * 4 + 2][r] = pa[i].z;
            As[buf][c4 * 4 + 3][r] = pa[i].w;
        }
        #pragma unroll
        for (int i = 0; i < NB; i++) {
            int idx = tid + i * NT;
            int r   = idx / (BNv / 4);
            int c4  = idx % (BNv / 4);
            *(float4*)&Bs[buf][r][c4 * 4] = pb[i];
        }
    };

    loadG(0);
    storeS(0);
    __syncthreads();

    const int nIter = (K + BKv - 1) / BKv;
    int buf = 0;
    for (int it = 0; it < nIter; it++) {
        if (it + 1 < nIter) loadG((it + 1) * BKv);

        #pragma unroll
        for (int kk = 0; kk < BKv; kk++) {
            float a[8], b[8];
            *(float4*)(a)     = *(const float4*)&As[buf][kk][ty * 4];
            *(float4*)(a + 4) = *(const float4*)&As[buf][kk][MH + ty * 4];
            *(float4*)(b)     = *(const float4*)&Bs[buf][kk][tx * 4];
            *(float4*)(b + 4) = *(const float4*)&Bs[buf][kk][NH + tx * 4];
            #pragma unroll
            for (int i = 0; i < 8; i++)
                #pragma unroll
                for (int j = 0; j < 8; j++)
                    acc[i][j] = fmaf(a[i], b[j], acc[i][j]);
        }

        if (it + 1 < nIter) storeS(buf ^ 1);
        __syncthreads();
        buf ^= 1;
    }

    // ---- epilogue ----
    float bv[8];
    if (BIAS_RELU) {
        #pragma unroll
        for (int jh = 0; jh < 2; jh++) {
            float4 t = *(const float4*)(bias + bn + jh * NH + tx * 4);
            bv[jh * 4 + 0] = t.x; bv[jh * 4 + 1] = t.y;
            bv[jh * 4 + 2] = t.z; bv[jh * 4 + 3] = t.w;
        }
    }
    #pragma unroll
    for (int ih = 0; ih < 2; ih++) {
        #pragma unroll
        for (int i = 0; i < 4; i++) {
            int r = bm + ih * MH + ty * 4 + i;
            if (r < M) {
                #pragma unroll
                for (int jh = 0; jh < 2; jh++) {
                    float4 o;
                    float v0 = acc[ih * 4 + i][jh * 4 + 0];
                    float v1 = acc[ih * 4 + i][jh * 4 + 1];
                    float v2 = acc[ih * 4 + i][jh * 4 + 2];
                    float v3 = acc[ih * 4 + i][jh * 4 + 3];
                    if (BIAS_RELU) {
                        v0 = fmaxf(v0 + bv[jh * 4 + 0], 0.f);
                        v1 = fmaxf(v1 + bv[jh * 4 + 1], 0.f);
                        v2 = fmaxf(v2 + bv[jh * 4 + 2], 0.f);
                        v3 = fmaxf(v3 + bv[jh * 4 + 3], 0.f);
                    }
                    o.x = v0; o.y = v1; o.z = v2; o.w = v3;
                    *(float4*)(C + (size_t)r * nc + bn + jh * NH + tx * 4) = o;
                }
            }
        }
    }
}

// =================================================================================
// CSR construction: count -> hierarchical scan -> scatter
// =================================================================================
__global__ void zero_kernel(int* p, int n)
{
    int i = blockIdx.x * blockDim.x + threadIdx.x;
    if (i < n) p[i] = 0;
}

__global__ void count_kernel(const int* __restrict__ rows, int* __restrict__ cnt, int E)
{
    int e = blockIdx.x * blockDim.x + threadIdx.x;
    if (e < E) atomicAdd(&cnt[rows[e]], 1);
}

// Phase 1: per-block (1024 elems) sum
__global__ void __launch_bounds__(256)
deg_reduce(const int* __restrict__ cnt, int* __restrict__ bsum, int n)
{
    __shared__ int sh[256];
    int t = threadIdx.x;
    int base = blockIdx.x * 1024 + t * 4;
    int s = 0;
    if (base + 3 < n) {
        int4 v = *(const int4*)(cnt + base);
        s = v.x + v.y + v.z + v.w;
    } else {
        for (int i = 0; i < 4; i++) if (base + i < n) s += cnt[base + i];
    }
    sh[t] = s;
    __syncthreads();
    for (int d = 128; d > 0; d >>= 1) {
        if (t < d) sh[t] += sh[t + d];
        __syncthreads();
    }
    if (t == 0) bsum[blockIdx.x] = sh[0];
}

// Phase 2: exclusive scan of block sums (nb <= 256), single block
__global__ void __launch_bounds__(256)
scan_bsums(int* bsum, int nb)
{
    __shared__ int sh[256];
    int t = threadIdx.x;
    int v = (t < nb) ? bsum[t] : 0;
    sh[t] = v;
    __syncthreads();
    for (int d = 1; d < 256; d <<= 1) {
        int u = (t >= d) ? sh[t - d] : 0;
        __syncthreads();
        sh[t] += u;
        __syncthreads();
    }
    if (t < nb) bsum[t] = sh[t] - v;   // exclusive
}

// Phase 3: per-block scan + add prefix, emit off[] and cur[]
__global__ void __launch_bounds__(256)
scan_apply(const int* __restrict__ cnt, const int* __restrict__ bsum,
           int* __restrict__ off, int* __restrict__ cur, int n, int E)
{
    __shared__ int sh[256];
    int t = threadIdx.x;
    int base = blockIdx.x * 1024 + t * 4;
    int c[4];
    int s = 0;
    #pragma unroll
    for (int i = 0; i < 4; i++) {
        c[i] = (base + i < n) ? cnt[base + i] : 0;
        s += c[i];
    }
    sh[t] = s;
    __syncthreads();
    for (int d = 1; d < 256; d <<= 1) {
        int u = (t >= d) ? sh[t - d] : 0;
        __syncthreads();
        sh[t] += u;
        __syncthreads();
    }
    int pre = bsum[blockIdx.x] + sh[t] - s;
    #pragma unroll
    for (int i = 0; i < 4; i++) {
        if (base + i < n) {
            off[base + i] = pre;
            cur[base + i] = pre;
            pre += c[i];
        }
    }
    if (blockIdx.x == 0 && t == 0) off[n] = E;
}

__global__ void scatter_kernel(const int* __restrict__ rows, const int* __restrict__ cols,
                               const float* __restrict__ vals, int* __restrict__ cur,
                               int* __restrict__ scols, float* __restrict__ svals, int E)
{
    int e = blockIdx.x * blockDim.x + threadIdx.x;
    if (e < E) {
        int p = atomicAdd(&cur[rows[e]], 1);
        scols[p] = cols[e];
        svals[p] = vals[e];
    }
}

// ---------------- row-per-warp SpMM: out[r,:] = (sum_e vals*dense[cols]) + bias ----
template<int NC, bool RELU>
__global__ void __launch_bounds__(256)
spmm_kernel(const int* __restrict__ off, const int* __restrict__ scols,
            const float* __restrict__ svals, const float* __restrict__ dense,
            const float* __restrict__ bias,
            float* __restrict__ out, int ldo,
            float* __restrict__ out2, int ldo2, int n)
{
    const int warp = (blockIdx.x * blockDim.x + threadIdx.x) >> 5;
    const int lane = threadIdx.x & 31;
    if (warp >= n) return;

    const int s = off[warp];
    const int e = off[warp + 1];
    constexpr int V = NC / 32;

    float acc[V];
    #pragma unroll
    for (int i = 0; i < V; i++) acc[i] = 0.f;

    int j = s;
    for (; j + 1 < e; j += 2) {
        const int   c0 = scols[j],     c1 = scols[j + 1];
        const float v0 = svals[j],     v1 = svals[j + 1];
        const float* d0 = dense + (size_t)c0 * NC;
        const float* d1 = dense + (size_t)c1 * NC;
        #pragma unroll
        for (int i = 0; i < V; i++) {
            acc[i] = fmaf(v0, d0[lane + 32 * i], acc[i]);
            acc[i] = fmaf(v1, d1[lane + 32 * i], acc[i]);
        }
    }
    if (j < e) {
        const int   c = scols[j];
        const float v = svals[j];
        const float* dr = dense + (size_t)c * NC;
        #pragma unroll
        for (int i = 0; i < V; i++)
            acc[i] = fmaf(v, dr[lane + 32 * i], acc[i]);
    }

    #pragma unroll
    for (int i = 0; i < V; i++) {
        float r = acc[i] + bias[lane + 32 * i];
        if (RELU) r = fmaxf(r, 0.f);
        out[(size_t)warp * ldo + lane + 32 * i] = r;
        if (out2) out2[(size_t)warp * ldo2 + lane + 32 * i] = r;
    }
}

// ---------------- DEC soft assignment q ----------------
__global__ void __launch_bounds__(256)
q_kernel(const float* __restrict__ zf, const float* __restrict__ cluster,
         float* __restrict__ q, int n)
{
    __shared__ float cs[KCLUS * EMB];
    for (int i = threadIdx.x; i < KCLUS * EMB; i += blockDim.x) cs[i] = cluster[i];
    __syncthreads();

    int nid = blockIdx.x * blockDim.x + threadIdx.x;
    if (nid >= n) return;

    float z[EMB];
    const float* zr = zf + (size_t)nid * EMB;
    #pragma unroll
    for (int i = 0; i < EMB; i++) z[i] = zr[i];

    float qq[KCLUS];
    float s = 0.f;
    #pragma unroll
    for (int k = 0; k < KCLUS; k++) {
        float d = 0.f;
        #pragma unroll
        for (int i = 0; i < EMB; i++) {
            float diff = z[i] - cs[k * EMB + i];
            d = fmaf(diff, diff, d);
        }
        qq[k] = 1.f / (1.f + d);
        s += qq[k];
    }
    float inv = 1.f / s;
    #pragma unroll
    for (int k = 0; k < KCLUS; k++)
        q[(size_t)nid * KCLUS + k] = qq[k] * inv;
}

// ---------------- host launcher ----------------
extern "C" void kernel_launch(void* const* d_in, const int* in_sizes, int n_in,
                              void* d_out, int out_size)
{
    float *xw, *h, *hw, *zcat, *svals;
    int *cnt, *off, *cur, *scols, *bsum;
    cudaGetSymbolAddress((void**)&xw,    g_xw);
    cudaGetSymbolAddress((void**)&h,     g_h);
    cudaGetSymbolAddress((void**)&hw,    g_hw);
    cudaGetSymbolAddress((void**)&zcat,  g_zcat);
    cudaGetSymbolAddress((void**)&cnt,   g_cnt);
    cudaGetSymbolAddress((void**)&off,   g_off);
    cudaGetSymbolAddress((void**)&cur,   g_cur);
    cudaGetSymbolAddress((void**)&scols, g_scols);
    cudaGetSymbolAddress((void**)&svals, g_svals);
    cudaGetSymbolAddress((void**)&bsum,  g_bsum);

    float* out = (float*)d_out;
    const int N = NNODES;

    // Input ordering detection (dict order vs reference-signature order).
    int IX[3], IR[3], IC[3], IV[3], IW1[3], IB1[3], IW2[3], IB2[3], IFW, IFB, ICL;
    bool dictOrder = (n_in >= 3) && (in_sizes[1] == in_sizes[2]) && (in_sizes[1] < in_sizes[0]);
    if (dictOrder) {
        for (int v = 0; v < 3; v++) {
            IX[v] = 8 * v + 0; IR[v] = 8 * v + 1; IC[v] = 8 * v + 2; IV[v] = 8 * v + 3;
            IW1[v] = 8 * v + 4; IB1[v] = 8 * v + 5; IW2[v] = 8 * v + 6; IB2[v] = 8 * v + 7;
        }
        IFW = 24; IFB = 25; ICL = 26;
    } else {
        for (int v = 0; v < 3; v++) {
            IX[v] = v;
            IR[v] = 3 + 3 * v; IC[v] = 4 + 3 * v; IV[v] = 5 + 3 * v;
            IW1[v] = 12 + 4 * v; IB1[v] = 13 + 4 * v; IW2[v] = 14 + 4 * v; IB2[v] = 15 + 4 * v;
        }
        IFW = 24; IFB = 25; ICL = 26;
    }

    for (int v = 0; v < 3; v++) {
        const float* x    = (const float*)d_in[IX[v]];
        const int*   rows = (const int*)  d_in[IR[v]];
        const int*   cols = (const int*)  d_in[IC[v]];
        const float* vals = (const float*)d_in[IV[v]];
        const float* w1   = (const float*)d_in[IW1[v]];
        const float* b1   = (const float*)d_in[IB1[v]];
        const float* w2   = (const float*)d_in[IW2[v]];
        const float* b2   = (const float*)d_in[IB2[v]];
        const int din = in_sizes[IX[v]] / N;
        const int E   = in_sizes[IR[v]];
        const int nb  = (N + 1023) / 1024;

        // GEMM1: xw = x @ w1   [N, HID]  (128x128 tile)
        {
            dim3 grid((N + 127) / 128, HID / 128);
            sgemm_tile<128, 128, 16, 256, false><<<grid, 256>>>(x, w1, nullptr, xw, N, din, HID);
        }
        // CSR build
        zero_kernel<<<(N + 255) / 256, 256>>>(cnt, N);
        count_kernel<<<(E + 255) / 256, 256>>>(rows, cnt, E);
        deg_reduce<<<nb, 256>>>(cnt, bsum, N);
        scan_bsums<<<1, 256>>>(bsum, nb);
        scan_apply<<<nb, 256>>>(cnt, bsum, off, cur, N, E);
        scatter_kernel<<<(E + 255) / 256, 256>>>(rows, cols, vals, cur, scols, svals, E);
        // SpMM1 + bias + relu -> h [N, HID]
        spmm_kernel<HID, true><<<(N + 7) / 8, 256>>>(off, scols, svals, xw, b1,
                                                     h, HID, nullptr, 0, N);
        // GEMM2: hw = h @ w2  [N, EMB]  (128x64 tile)
        {
            dim3 grid((N + 127) / 128, EMB / 64);
            sgemm_tile<128, 64, 16, 128, false><<<grid, 128>>>(h, w2, nullptr, hw, N, HID, EMB);
        }
        // SpMM2 + bias -> z_v, dual-write into d_out and concat buffer
        spmm_kernel<EMB, false><<<(N + 7) / 8, 256>>>(off, scols, svals, hw, b2,
                                                      out + (size_t)v * N * EMB, EMB,
                                                      zcat + (size_t)v * EMB, 3 * EMB, N);
    }

    const float* fw = (const float*)d_in[IFW];
    const float* fb = (const float*)d_in[IFB];
    const float* cl = (const float*)d_in[ICL];
    float* zf = out + (size_t)3 * N * EMB;
    float* qp = out + (size_t)4 * N * EMB;

    // fusion: zf = relu(zcat @ fusion_w + fusion_b)  [N, EMB]
    {
        dim3 grid((N + 127) / 128, EMB / 64);
        sgemm_tile<128, 64, 16, 128, true><<<grid, 128>>>(zcat, fw, fb, zf, N, 3 * EMB, EMB);
    }
    // Student-t soft assignment
    q_kernel<<<(N + 255) / 256, 256>>>(zf, cl, qp, N);
}

// round 5
// speedup vs baseline: 1.6470x; 1.6470x over previous
#include <cuda_runtime.h>
#include <cstdint>

#define NNODES 50000
#define MAXEDGES 800000
#define HID 128
#define EMB 64
#define KCLUS 10

// ---------------- scratch (device globals; no allocation allowed) ----------------
__device__ float g_xw  [NNODES * HID];        // x @ w1
__device__ float g_h   [NNODES * HID];        // relu(spmm + b1)
__device__ float g_hw  [NNODES * EMB];        // h @ w2
__device__ float g_zcat[NNODES * 3 * EMB];    // concat(z0,z1,z2)
__device__ int   g_cnt [NNODES];
__device__ int   g_off [NNODES + 1];
__device__ int   g_cur [NNODES];
__device__ int   g_scols[MAXEDGES];
__device__ float g_svals[MAXEDGES];
__device__ int   g_bsum[64];                  // block sums for hierarchical scan

// ---------------- tiled fp32 SGEMM (round-1 proven version) ---------------------
// BM=128, BN=64, BK=8, 256 threads, thread tile 8x4.
#define BM 128
#define BN 64
#define BK 8
#define TM 8
#define TN 4

template<bool EPI_BIAS_RELU>
__global__ void __launch_bounds__(256)
sgemm_kernel(const float* __restrict__ A, const float* __restrict__ B,
             const float* __restrict__ bias, float* __restrict__ C,
             int M, int K, int nc)
{
    __shared__ float As[BK][BM];
    __shared__ float Bs[BK][BN];

    const int tid = threadIdx.x;
    const int bm  = blockIdx.x * BM;
    const int bn  = blockIdx.y * BN;
    const int tx  = tid & 15;     // 0..15 -> n offset tx*4
    const int ty  = tid >> 4;     // 0..15 -> m offset ty*8

    float acc[TM][TN];
    #pragma unroll
    for (int i = 0; i < TM; i++)
        #pragma unroll
        for (int j = 0; j < TN; j++) acc[i][j] = 0.f;

    // A tile load mapping: 128 rows x 8 k, one float4 per thread
    const int arow = tid >> 1;            // 0..127
    const int acol = (tid & 1) * 4;       // 0 or 4
    // B tile load mapping: 8 rows x 64 cols, one float2 per thread
    const int brow = tid >> 5;            // 0..7
    const int bcol = (tid & 31) * 2;      // 0..62

    const bool avalid = (bm + arow) < M;
    const float* Abase = A + (size_t)(bm + arow) * K + acol;
    const float* Bbase = B + (size_t)brow * nc + bn + bcol;

    for (int k0 = 0; k0 < K; k0 += BK) {
        float4 av = make_float4(0.f, 0.f, 0.f, 0.f);
        if (avalid) av = *(const float4*)(Abase + k0);
        As[acol + 0][arow] = av.x;
        As[acol + 1][arow] = av.y;
        As[acol + 2][arow] = av.z;
        As[acol + 3][arow] = av.w;

        float2 bv = *(const float2*)(Bbase + (size_t)k0 * nc);
        Bs[brow][bcol]     = bv.x;
        Bs[brow][bcol + 1] = bv.y;
        __syncthreads();

        #pragma unroll
        for (int kk = 0; kk < BK; kk++) {
            float4 a0 = *(const float4*)&As[kk][ty * TM];
            float4 a1 = *(const float4*)&As[kk][ty * TM + 4];
            float4 b0 = *(const float4*)&Bs[kk][tx * TN];
            float a[TM] = {a0.x, a0.y, a0.z, a0.w, a1.x, a1.y, a1.z, a1.w};
            float b[TN] = {b0.x, b0.y, b0.z, b0.w};
            #pragma unroll
            for (int i = 0; i < TM; i++)
                #pragma unroll
                for (int j = 0; j < TN; j++)
                    acc[i][j] = fmaf(a[i], b[j], acc[i][j]);
        }
        __syncthreads();
    }

    float bv[TN] = {0.f, 0.f, 0.f, 0.f};
    if (EPI_BIAS_RELU) {
        #pragma unroll
        for (int j = 0; j < TN; j++) bv[j] = bias[bn + tx * TN + j];
    }

    #pragma unroll
    for (int i = 0; i < TM; i++) {
        int r = bm + ty * TM + i;
        if (r < M) {
            float4 o;
            float v0 = acc[i][0], v1 = acc[i][1], v2 = acc[i][2], v3 = acc[i][3];
            if (EPI_BIAS_RELU) {
                v0 = fmaxf(v0 + bv[0], 0.f);
                v1 = fmaxf(v1 + bv[1], 0.f);
                v2 = fmaxf(v2 + bv[2], 0.f);
                v3 = fmaxf(v3 + bv[3], 0.f);
            }
            o.x = v0; o.y = v1; o.z = v2; o.w = v3;
            *(float4*)(C + (size_t)r * nc + bn + tx * TN) = o;
        }
    }
}

// =================================================================================
// CSR construction: count -> hierarchical scan (3 kernels) -> scatter
// =================================================================================
__global__ void zero_kernel(int* p, int n)
{
    int i = blockIdx.x * blockDim.x + threadIdx.x;
    if (i < n) p[i] = 0;
}

__global__ void count_kernel(const int* __restrict__ rows, int* __restrict__ cnt, int E)
{
    int e = blockIdx.x * blockDim.x + threadIdx.x;
    if (e < E) atomicAdd(&cnt[rows[e]], 1);
}

// Phase 1: per-block (1024 elems) sum
__global__ void __launch_bounds__(256)
deg_reduce(const int* __restrict__ cnt, int* __restrict__ bsum, int n)
{
    __shared__ int sh[256];
    int t = threadIdx.x;
    int base = blockIdx.x * 1024 + t * 4;
    int s = 0;
    if (base + 3 < n) {
        int4 v = *(const int4*)(cnt + base);
        s = v.x + v.y + v.z + v.w;
    } else {
        for (int i = 0; i < 4; i++) if (base + i < n) s += cnt[base + i];
    }
    sh[t] = s;
    __syncthreads();
    for (int d = 128; d > 0; d >>= 1) {
        if (t < d) sh[t] += sh[t + d];
        __syncthreads();
    }
    if (t == 0) bsum[blockIdx.x] = sh[0];
}

// Phase 2: exclusive scan of block sums (nb <= 256), single block
__global__ void __launch_bounds__(256)
scan_bsums(int* bsum, int nb)
{
    __shared__ int sh[256];
    int t = threadIdx.x;
    int v = (t < nb) ? bsum[t] : 0;
    sh[t] = v;
    __syncthreads();
    for (int d = 1; d < 256; d <<= 1) {
        int u = (t >= d) ? sh[t - d] : 0;
        __syncthreads();
        sh[t] += u;
        __syncthreads();
    }
    if (t < nb) bsum[t] = sh[t] - v;   // exclusive
}

// Phase 3: per-block scan + add prefix, emit off[] and cur[]
__global__ void __launch_bounds__(256)
scan_apply(const int* __restrict__ cnt, const int* __restrict__ bsum,
           int* __restrict__ off, int* __restrict__ cur, int n, int E)
{
    __shared__ int sh[256];
    int t = threadIdx.x;
    int base = blockIdx.x * 1024 + t * 4;
    int c[4];
    int s = 0;
    #pragma unroll
    for (int i = 0; i < 4; i++) {
        c[i] = (base + i < n) ? cnt[base + i] : 0;
        s += c[i];
    }
    sh[t] = s;
    __syncthreads();
    for (int d = 1; d < 256; d <<= 1) {
        int u = (t >= d) ? sh[t - d] : 0;
        __syncthreads();
        sh[t] += u;
        __syncthreads();
    }
    int pre = bsum[blockIdx.x] + sh[t] - s;
    #pragma unroll
    for (int i = 0; i < 4; i++) {
        if (base + i < n) {
            off[base + i] = pre;
            cur[base + i] = pre;
            pre += c[i];
        }
    }
    if (blockIdx.x == 0 && t == 0) off[n] = E;
}

__global__ void scatter_kernel(const int* __restrict__ rows, const int* __restrict__ cols,
                               const float* __restrict__ vals, int* __restrict__ cur,
                               int* __restrict__ scols, float* __restrict__ svals, int E)
{
    int e = blockIdx.x * blockDim.x + threadIdx.x;
    if (e < E) {
        int p = atomicAdd(&cur[rows[e]], 1);
        scols[p] = cols[e];
        svals[p] = vals[e];
    }
}

// ---------------- row-per-warp SpMM: out[r,:] = (sum_e vals*dense[cols]) + bias ----
template<int NC, bool RELU>
__global__ void __launch_bounds__(256)
spmm_kernel(const int* __restrict__ off, const int* __restrict__ scols,
            const float* __restrict__ svals, const float* __restrict__ dense,
            const float* __restrict__ bias,
            float* __restrict__ out, int ldo,
            float* __restrict__ out2, int ldo2, int n)
{
    const int warp = (blockIdx.x * blockDim.x + threadIdx.x) >> 5;
    const int lane = threadIdx.x & 31;
    if (warp >= n) return;

    const int s = off[warp];
    const int e = off[warp + 1];
    constexpr int V = NC / 32;

    float acc[V];
    #pragma unroll
    for (int i = 0; i < V; i++) acc[i] = 0.f;

    int j = s;
    for (; j + 1 < e; j += 2) {
        const int   c0 = scols[j],     c1 = scols[j + 1];
        const float v0 = svals[j],     v1 = svals[j + 1];
        const float* d0 = dense + (size_t)c0 * NC;
        const float* d1 = dense + (size_t)c1 * NC;
        #pragma unroll
        for (int i = 0; i < V; i++) {
            acc[i] = fmaf(v0, d0[lane + 32 * i], acc[i]);
            acc[i] = fmaf(v1, d1[lane + 32 * i], acc[i]);
        }
    }
    if (j < e) {
        const int   c = scols[j];
        const float v = svals[j];
        const float* dr = dense + (size_t)c * NC;
        #pragma unroll
        for (int i = 0; i < V; i++)
            acc[i] = fmaf(v, dr[lane + 32 * i], acc[i]);
    }

    #pragma unroll
    for (int i = 0; i < V; i++) {
        float r = acc[i] + bias[lane + 32 * i];
        if (RELU) r = fmaxf(r, 0.f);
        out[(size_t)warp * ldo + lane + 32 * i] = r;
        if (out2) out2[(size_t)warp * ldo2 + lane + 32 * i] = r;
    }
}

// ---------------- DEC soft assignment q ----------------
__global__ void __launch_bounds__(256)
q_kernel(const float* __restrict__ zf, const float* __restrict__ cluster,
         float* __restrict__ q, int n)
{
    __shared__ float cs[KCLUS * EMB];
    for (int i = threadIdx.x; i < KCLUS * EMB; i += blockDim.x) cs[i] = cluster[i];
    __syncthreads();

    int nid = blockIdx.x * blockDim.x + threadIdx.x;
    if (nid >= n) return;

    float z[EMB];
    const float* zr = zf + (size_t)nid * EMB;
    #pragma unroll
    for (int i = 0; i < EMB; i++) z[i] = zr[i];

    float qq[KCLUS];
    float s = 0.f;
    #pragma unroll
    for (int k = 0; k < KCLUS; k++) {
        float d = 0.f;
        #pragma unroll
        for (int i = 0; i < EMB; i++) {
            float diff = z[i] - cs[k * EMB + i];
            d = fmaf(diff, diff, d);
        }
        qq[k] = 1.f / (1.f + d);
        s += qq[k];
    }
    float inv = 1.f / s;
    #pragma unroll
    for (int k = 0; k < KCLUS; k++)
        q[(size_t)nid * KCLUS + k] = qq[k] * inv;
}

// ---------------- host launcher ----------------
extern "C" void kernel_launch(void* const* d_in, const int* in_sizes, int n_in,
                              void* d_out, int out_size)
{
    float *xw, *h, *hw, *zcat, *svals;
    int *cnt, *off, *cur, *scols, *bsum;
    cudaGetSymbolAddress((void**)&xw,    g_xw);
    cudaGetSymbolAddress((void**)&h,     g_h);
    cudaGetSymbolAddress((void**)&hw,    g_hw);
    cudaGetSymbolAddress((void**)&zcat,  g_zcat);
    cudaGetSymbolAddress((void**)&cnt,   g_cnt);
    cudaGetSymbolAddress((void**)&off,   g_off);
    cudaGetSymbolAddress((void**)&cur,   g_cur);
    cudaGetSymbolAddress((void**)&scols, g_scols);
    cudaGetSymbolAddress((void**)&svals, g_svals);
    cudaGetSymbolAddress((void**)&bsum,  g_bsum);

    float* out = (float*)d_out;
    const int N = NNODES;

    // Input ordering detection (dict order vs reference-signature order).
    int IX[3], IR[3], IC[3], IV[3], IW1[3], IB1[3], IW2[3], IB2[3], IFW, IFB, ICL;
    bool dictOrder = (n_in >= 3) && (in_sizes[1] == in_sizes[2]) && (in_sizes[1] < in_sizes[0]);
    if (dictOrder) {
        for (int v = 0; v < 3; v++) {
            IX[v] = 8 * v + 0; IR[v] = 8 * v + 1; IC[v] = 8 * v + 2; IV[v] = 8 * v + 3;
            IW1[v] = 8 * v + 4; IB1[v] = 8 * v + 5; IW2[v] = 8 * v + 6; IB2[v] = 8 * v + 7;
        }
        IFW = 24; IFB = 25; ICL = 26;
    } else {
        for (int v = 0; v < 3; v++) {
            IX[v] = v;
            IR[v] = 3 + 3 * v; IC[v] = 4 + 3 * v; IV[v] = 5 + 3 * v;
            IW1[v] = 12 + 4 * v; IB1[v] = 13 + 4 * v; IW2[v] = 14 + 4 * v; IB2[v] = 15 + 4 * v;
        }
        IFW = 24; IFB = 25; ICL = 26;
    }

    for (int v = 0; v < 3; v++) {
        const float* x    = (const float*)d_in[IX[v]];
        const int*   rows = (const int*)  d_in[IR[v]];
        const int*   cols = (const int*)  d_in[IC[v]];
        const float* vals = (const float*)d_in[IV[v]];
        const float* w1   = (const float*)d_in[IW1[v]];
        const float* b1   = (const float*)d_in[IB1[v]];
        const float* w2   = (const float*)d_in[IW2[v]];
        const float* b2   = (const float*)d_in[IB2[v]];
        const int din = in_sizes[IX[v]] / N;
        const int E   = in_sizes[IR[v]];
        const int nb  = (N + 1023) / 1024;

        // GEMM1: xw = x @ w1   [N, HID]
        {
            dim3 grid((N + BM - 1) / BM, HID / BN);
            sgemm_kernel<false><<<grid, 256>>>(x, w1, nullptr, xw, N, din, HID);
        }
        // CSR build (hierarchical scan)
        zero_kernel<<<(N + 255) / 256, 256>>>(cnt, N);
        count_kernel<<<(E + 255) / 256, 256>>>(rows, cnt, E);
        deg_reduce<<<nb, 256>>>(cnt, bsum, N);
        scan_bsums<<<1, 256>>>(bsum, nb);
        scan_apply<<<nb, 256>>>(cnt, bsum, off, cur, N, E);
        scatter_kernel<<<(E + 255) / 256, 256>>>(rows, cols, vals, cur, scols, svals, E);
        // SpMM1 + bias + relu -> h [N, HID]
        spmm_kernel<HID, true><<<(N + 7) / 8, 256>>>(off, scols, svals, xw, b1,
                                                     h, HID, nullptr, 0, N);
        // GEMM2: hw = h @ w2  [N, EMB]
        {
            dim3 grid((N + BM - 1) / BM, EMB / BN);
            sgemm_kernel<false><<<grid, 256>>>(h, w2, nullptr, hw, N, HID, EMB);
        }
        // SpMM2 + bias -> z_v, dual-write into d_out and concat buffer
        spmm_kernel<EMB, false><<<(N + 7) / 8, 256>>>(off, scols, svals, hw, b2,
                                                      out + (size_t)v * N * EMB, EMB,
                                                      zcat + (size_t)v * EMB, 3 * EMB, N);
    }

    const float* fw = (const float*)d_in[IFW];
    const float* fb = (const float*)d_in[IFB];
    const float* cl = (const float*)d_in[ICL];
    float* zf = out + (size_t)3 * N * EMB;
    float* qp = out + (size_t)4 * N * EMB;

    // fusion: zf = relu(zcat @ fusion_w + fusion_b)  [N, EMB]
    {
        dim3 grid((N + BM - 1) / BM, EMB / BN);
        sgemm_kernel<true><<<grid, 256>>>(zcat, fw, fb, zf, N, 3 * EMB, EMB);
    }
    // Student-t soft assignment
    q_kernel<<<(N + 255) / 256, 256>>>(zf, cl, qp, N);
}